// round 3
// baseline (speedup 1.0000x reference)
#include <cuda_runtime.h>
#include <cstdint>

// SLAYER constants
#define ALPHA_F 0.90483741803595952f   // exp(-TS/TAU_SR), rounded to f32 like JAX does
#define THETA_F 10.0f

// Problem dims
#define BB   32
#define CIN  156
#define TT   2048
#define HID  512
#define NOUT 20
#define OUTT (TT + CIN)   // 2204

// ---------------------------------------------------------------------------
// Scratch (static __device__ arrays — no runtime allocation)
// ---------------------------------------------------------------------------
__device__ float g_s1[(size_t)BB * HID * TT];   // branch1 layer1 acts -> spikes (134MB)
__device__ float g_a2[(size_t)BB * NOUT * TT];  // branch1 layer2 pre-acts
__device__ float g_l1[(size_t)BB * HID * CIN];  // branch2 layer1 acts -> spikes
__device__ float g_l2[(size_t)BB * NOUT * CIN]; // branch2 layer2 pre-acts

// ---------------------------------------------------------------------------
// Branch1 layer1: a1[b,h,t] = sum_c W1[h,c] * X[b,c,t]
// Tile 64h x 64t, K=156 padded to 160 (trailing zeros -> rounding-exact),
// k strictly ascending in a single FMA chain per output (cublas-like order).
// ---------------------------------------------------------------------------
__global__ __launch_bounds__(256) void k_gemm_b1l1(const float* __restrict__ X,
                                                   const float* __restrict__ W1) {
    __shared__ float Ws[16][65];
    __shared__ float Xs[16][65];
    const int b  = blockIdx.z;
    const int h0 = blockIdx.y * 64;
    const int t0 = blockIdx.x * 64;
    const int tid = threadIdx.x;
    const float* Xb = X + (size_t)b * CIN * TT;

    float acc[4][4];
#pragma unroll
    for (int i = 0; i < 4; i++)
#pragma unroll
        for (int j = 0; j < 4; j++) acc[i][j] = 0.0f;

    const int hr = tid >> 4, tc = tid & 15;

    for (int k0 = 0; k0 < 160; k0 += 16) {
#pragma unroll
        for (int i = 0; i < 4; i++) {
            int idx = tid + 256 * i;          // 0..1023
            int h = idx >> 4, k = idx & 15;
            int kk = k0 + k;
            Ws[k][h] = (kk < CIN) ? W1[(h0 + h) * CIN + kk] : 0.0f;
        }
#pragma unroll
        for (int i = 0; i < 4; i++) {
            int idx = tid + 256 * i;
            int k = idx >> 6, t = idx & 63;
            int kk = k0 + k;
            Xs[k][t] = (kk < CIN) ? Xb[(size_t)kk * TT + t0 + t] : 0.0f;
        }
        __syncthreads();
#pragma unroll
        for (int k = 0; k < 16; k++) {
            float wv[4], xv[4];
#pragma unroll
            for (int i = 0; i < 4; i++) wv[i] = Ws[k][hr * 4 + i];
#pragma unroll
            for (int j = 0; j < 4; j++) xv[j] = Xs[k][tc * 4 + j];
#pragma unroll
            for (int i = 0; i < 4; i++)
#pragma unroll
                for (int j = 0; j < 4; j++)
                    acc[i][j] = fmaf(wv[i], xv[j], acc[i][j]);
        }
        __syncthreads();
    }

    float* op = g_s1 + ((size_t)b * HID + h0) * TT + t0;
#pragma unroll
    for (int i = 0; i < 4; i++)
#pragma unroll
        for (int j = 0; j < 4; j++)
            op[(size_t)(hr * 4 + i) * TT + tc * 4 + j] = acc[i][j];
}

// ---------------------------------------------------------------------------
// psp + spike, strictly sequential per row (matches lax.scan ordering),
// in-place. len must be divisible by 4.
// ---------------------------------------------------------------------------
__device__ __forceinline__ void psp_row_inplace(float* p, int len4) {
    float4* pv = (float4*)p;
    float y = 0.0f;
    for (int t = 0; t < len4; t++) {
        float4 v = pv[t];
        float4 s;
        y = fmaf(ALPHA_F, y, v.x); s.x = (y >= THETA_F) ? 1.0f : 0.0f;
        y = fmaf(ALPHA_F, y, v.y); s.y = (y >= THETA_F) ? 1.0f : 0.0f;
        y = fmaf(ALPHA_F, y, v.z); s.z = (y >= THETA_F) ? 1.0f : 0.0f;
        y = fmaf(ALPHA_F, y, v.w); s.w = (y >= THETA_F) ? 1.0f : 0.0f;
        pv[t] = s;
    }
}

__device__ __forceinline__ void psp_row_to(const float* p, float* q, int len) {
    float y = 0.0f;
    for (int t = 0; t < len; t++) {
        y = fmaf(ALPHA_F, y, p[t]);
        q[t] = (y >= THETA_F) ? 1.0f : 0.0f;
    }
}

__global__ void k_psp_s1() {
    int r = blockIdx.x * blockDim.x + threadIdx.x;
    if (r >= BB * HID) return;
    psp_row_inplace(g_s1 + (size_t)r * TT, TT / 4);
}

__global__ void k_psp_l1() {
    int r = blockIdx.x * blockDim.x + threadIdx.x;
    if (r >= BB * HID) return;
    psp_row_inplace(g_l1 + (size_t)r * CIN, CIN / 4);
}

__global__ void k_psp_a2_out(float* __restrict__ out) {
    int r = blockIdx.x * blockDim.x + threadIdx.x;   // r = b*NOUT + o
    if (r >= BB * NOUT) return;
    psp_row_to(g_a2 + (size_t)r * TT, out + (size_t)r * OUTT, TT);
}

__global__ void k_psp_l2_out(float* __restrict__ out) {
    int r = blockIdx.x * blockDim.x + threadIdx.x;
    if (r >= BB * NOUT) return;
    psp_row_to(g_l2 + (size_t)r * CIN, out + (size_t)r * OUTT + TT, CIN);
}

// ---------------------------------------------------------------------------
// Branch1 layer2: a2[b,o,t] = sum_h W2[o,h] * s1[b,h,t]
// Tile 32o(pad from 20) x 64t, K=512, k ascending single chain.
// ---------------------------------------------------------------------------
__global__ __launch_bounds__(128) void k_gemm_b1l2(const float* __restrict__ W2) {
    __shared__ float Ws[32][33];
    __shared__ float Ss[32][65];
    const int b  = blockIdx.z;
    const int t0 = blockIdx.x * 64;
    const int tid = threadIdx.x;
    const float* Sb = g_s1 + (size_t)b * HID * TT;

    float acc[4][4];
#pragma unroll
    for (int i = 0; i < 4; i++)
#pragma unroll
        for (int j = 0; j < 4; j++) acc[i][j] = 0.0f;

    const int og = tid >> 4, tg = tid & 15;

    for (int k0 = 0; k0 < HID; k0 += 32) {
#pragma unroll
        for (int i = 0; i < 8; i++) {
            int idx = tid + 128 * i;       // 0..1023
            int o = idx >> 5, k = idx & 31;
            Ws[k][o] = (o < NOUT) ? W2[o * HID + k0 + k] : 0.0f;
        }
#pragma unroll
        for (int i = 0; i < 16; i++) {
            int idx = tid + 128 * i;       // 0..2047
            int k = idx >> 6, t = idx & 63;
            Ss[k][t] = Sb[(size_t)(k0 + k) * TT + t0 + t];
        }
        __syncthreads();
#pragma unroll
        for (int k = 0; k < 32; k++) {
            float wv[4], xv[4];
#pragma unroll
            for (int i = 0; i < 4; i++) wv[i] = Ws[k][og * 4 + i];
#pragma unroll
            for (int j = 0; j < 4; j++) xv[j] = Ss[k][tg * 4 + j];
#pragma unroll
            for (int i = 0; i < 4; i++)
#pragma unroll
                for (int j = 0; j < 4; j++)
                    acc[i][j] = fmaf(wv[i], xv[j], acc[i][j]);
        }
        __syncthreads();
    }

#pragma unroll
    for (int i = 0; i < 4; i++) {
        int o = og * 4 + i;
        if (o < NOUT) {
#pragma unroll
            for (int j = 0; j < 4; j++)
                g_a2[((size_t)b * NOUT + o) * TT + t0 + tg * 4 + j] = acc[i][j];
        }
    }
}

// ---------------------------------------------------------------------------
// Branch2 layer1: l1a[b,h,c] = sum_t Wl1[h,t] * X[b,perm[c],t]
// NT-GEMM, tile 64h x 64c (c padded past 156), K=2048 ascending.
// ---------------------------------------------------------------------------
__global__ __launch_bounds__(256) void k_gemm_b2l1(const float* __restrict__ X,
                                                   const float* __restrict__ Wl1,
                                                   const int* __restrict__ perm) {
    __shared__ float As[16][65];
    __shared__ float Xs[16][65];
    __shared__ int prow[64];
    const int b  = blockIdx.z;
    const int h0 = blockIdx.y * 64;
    const int c0 = blockIdx.x * 64;
    const int tid = threadIdx.x;

    if (tid < 64) {
        int c = c0 + tid;
        prow[tid] = (c < CIN) ? perm[c] : 0;
    }
    __syncthreads();

    const float* Xb = X + (size_t)b * CIN * TT;
    float acc[4][4];
#pragma unroll
    for (int i = 0; i < 4; i++)
#pragma unroll
        for (int j = 0; j < 4; j++) acc[i][j] = 0.0f;

    const int hr = tid >> 4, cg = tid & 15;

    for (int k0 = 0; k0 < TT; k0 += 16) {
#pragma unroll
        for (int i = 0; i < 4; i++) {
            int idx = tid + 256 * i;
            int h = idx >> 4, k = idx & 15;
            As[k][h] = Wl1[(size_t)(h0 + h) * TT + k0 + k];
        }
#pragma unroll
        for (int i = 0; i < 4; i++) {
            int idx = tid + 256 * i;
            int c = idx >> 4, k = idx & 15;
            Xs[k][c] = Xb[(size_t)prow[c] * TT + k0 + k];
        }
        __syncthreads();
#pragma unroll
        for (int k = 0; k < 16; k++) {
            float wv[4], xv[4];
#pragma unroll
            for (int i = 0; i < 4; i++) wv[i] = As[k][hr * 4 + i];
#pragma unroll
            for (int j = 0; j < 4; j++) xv[j] = Xs[k][cg * 4 + j];
#pragma unroll
            for (int i = 0; i < 4; i++)
#pragma unroll
                for (int j = 0; j < 4; j++)
                    acc[i][j] = fmaf(wv[i], xv[j], acc[i][j]);
        }
        __syncthreads();
    }

#pragma unroll
    for (int i = 0; i < 4; i++)
#pragma unroll
        for (int j = 0; j < 4; j++) {
            int c = c0 + cg * 4 + j;
            if (c < CIN)
                g_l1[((size_t)b * HID + h0 + hr * 4 + i) * CIN + c] = acc[i][j];
        }
}

// ---------------------------------------------------------------------------
// Branch2 layer2: l2a[b,o,c] = sum_h Wl2[o,h] * l1[b,h,c]
// Block = (o-group of 4, b). Thread per c. h ascending (chunks of 4).
// ---------------------------------------------------------------------------
__global__ __launch_bounds__(160) void k_gemm_b2l2(const float* __restrict__ Wl2) {
    __shared__ float Ws[4 * HID];
    const int og = blockIdx.x;   // 0..4
    const int b  = blockIdx.y;
    const int tid = threadIdx.x;

    for (int idx = tid; idx < 4 * HID; idx += 160) {
        int o = idx >> 9, h = idx & 511;
        Ws[idx] = Wl2[(og * 4 + o) * HID + h];
    }
    __syncthreads();

    const int c = tid;
    if (c >= CIN) return;
    const float* Lb = g_l1 + (size_t)b * HID * CIN;
    float acc[4] = {0.0f, 0.0f, 0.0f, 0.0f};

    for (int h = 0; h < HID; h += 4) {
        float xv0 = Lb[(size_t)h * CIN + c];
        float xv1 = Lb[(size_t)(h + 1) * CIN + c];
        float xv2 = Lb[(size_t)(h + 2) * CIN + c];
        float xv3 = Lb[(size_t)(h + 3) * CIN + c];
#pragma unroll
        for (int o = 0; o < 4; o++) {
            const float4 w = *(const float4*)&Ws[o * HID + h];
            acc[o] = fmaf(w.x, xv0, acc[o]);
            acc[o] = fmaf(w.y, xv1, acc[o]);
            acc[o] = fmaf(w.z, xv2, acc[o]);
            acc[o] = fmaf(w.w, xv3, acc[o]);
        }
    }
#pragma unroll
    for (int o = 0; o < 4; o++)
        g_l2[((size_t)b * NOUT + og * 4 + o) * CIN + c] = acc[o];
}

// ---------------------------------------------------------------------------
// Launch
// ---------------------------------------------------------------------------
extern "C" void kernel_launch(void* const* d_in, const int* in_sizes, int n_in,
                              void* d_out, int out_size) {
    (void)in_sizes; (void)n_in; (void)out_size;
    const float* X    = (const float*)d_in[0];
    const float* W1   = (const float*)d_in[1];
    const float* W2   = (const float*)d_in[2];
    const float* Wl1  = (const float*)d_in[3];
    const float* Wl2  = (const float*)d_in[4];
    const int*   perm = (const int*)d_in[5];
    float* out = (float*)d_out;

    // Branch 1
    k_gemm_b1l1<<<dim3(TT / 64, HID / 64, BB), 256>>>(X, W1);
    k_psp_s1<<<(BB * HID + 255) / 256, 256>>>();
    k_gemm_b1l2<<<dim3(TT / 64, 1, BB), 128>>>(W2);
    k_psp_a2_out<<<(BB * NOUT + 255) / 256, 256>>>(out);

    // Branch 2
    k_gemm_b2l1<<<dim3((CIN + 63) / 64, HID / 64, BB), 256>>>(X, Wl1, perm);
    k_psp_l1<<<(BB * HID + 255) / 256, 256>>>();
    k_gemm_b2l2<<<dim3(5, BB), 160>>>(Wl2);
    k_psp_l2_out<<<(BB * NOUT + 255) / 256, 256>>>(out);
}

// round 4
// speedup vs baseline: 2.1481x; 2.1481x over previous
#include <cuda_runtime.h>
#include <cstdint>

// SLAYER constants
#define ALPHA_F 0.90483741803595952f
#define THETA_F 10.0f

// Problem dims
#define BB   32
#define CIN  156
#define TT   2048
#define HID  512
#define NOUT 20
#define OUTT (TT + CIN)   // 2204

// ---------------------------------------------------------------------------
// Scratch
// ---------------------------------------------------------------------------
__device__ float         g_s1[(size_t)BB * HID * TT];    // branch1 layer1 pre-acts (float)
__device__ unsigned char g_s1u8[(size_t)BB * HID * TT];  // branch1 layer1 spikes (u8)
__device__ float         g_a2[(size_t)BB * NOUT * TT];   // branch1 layer2 pre-acts
__device__ float         g_l1[(size_t)BB * CIN * HID];   // branch2 layer1, layout [b][c][h]
__device__ float         g_l2[(size_t)BB * NOUT * CIN];  // branch2 layer2 pre-acts

// packed fp32x2 FMA: two independent rn-rounded fp32 FMAs (bitwise == scalar fmaf)
__device__ __forceinline__ void ffma2(unsigned long long& d,
                                      unsigned long long a,
                                      unsigned long long b) {
    asm("fma.rn.f32x2 %0, %1, %2, %0;" : "+l"(d) : "l"(a), "l"(b));
}

// ---------------------------------------------------------------------------
// Branch1 layer1: a1[b,h,t] = sum_c W1[h,c] * X[b,c,t]
// 128h x 128t tile, BK=16 (K padded 156->160 with zeros), 256 threads, 8x8 micro.
// A stored duplicated (w,w) pairs in smem; inner loop is pure v2.u64 LDS + FFMA2.
// k strictly ascending, one accumulator chain per output -> bitwise as before.
// ---------------------------------------------------------------------------
__global__ __launch_bounds__(256) void k_gemm_b1l1(const float* __restrict__ X,
                                                   const float* __restrict__ W1) {
    __shared__ unsigned long long Asd[16 * 132];  // dup pairs, row stride 132 pairs
    __shared__ float Bsf[16 * 136];               // row stride 136 floats (68 pairs)

    const int b  = blockIdx.z;
    const int h0 = blockIdx.y * 128;
    const int t0 = blockIdx.x * 128;
    const int tid = threadIdx.x;
    const int tx = tid & 15;   // t micro (8 t each)
    const int ty = tid >> 4;   // h micro (8 h each)
    const float* Xb = X + (size_t)b * CIN * TT;

    unsigned long long acc[8][4];
#pragma unroll
    for (int i = 0; i < 8; i++)
#pragma unroll
        for (int j = 0; j < 4; j++) acc[i][j] = 0ULL;

    for (int k0 = 0; k0 < 160; k0 += 16) {
        // A slab: W1[h0..h0+127][k0..k0+15], zero pad c>=156, store (w,w) pairs
#pragma unroll
        for (int i = 0; i < 8; i++) {
            int idx = tid + 256 * i;        // 0..2047
            int h = idx >> 4, k = idx & 15;
            int c = k0 + k;
            float v = (c < CIN) ? W1[(h0 + h) * CIN + c] : 0.0f;
            ((float2*)Asd)[k * 132 + h] = make_float2(v, v);
        }
        // B slab: X[c][t0..t0+127]
#pragma unroll
        for (int i = 0; i < 2; i++) {
            int kk = (tid >> 5) + 8 * i;    // 0..15
            int t4 = (tid & 31) * 4;
            int c = k0 + kk;
            float4 v = make_float4(0.f, 0.f, 0.f, 0.f);
            if (c < CIN) v = *(const float4*)(Xb + (size_t)c * TT + t0 + t4);
            *(float4*)&Bsf[kk * 136 + t4] = v;
        }
        __syncthreads();
#pragma unroll
        for (int k = 0; k < 16; k++) {
            unsigned long long a[8], bq[4];
#pragma unroll
            for (int q = 0; q < 4; q++) {
                ulonglong2 aa = *(const ulonglong2*)(Asd + k * 132 + ty * 8 + 2 * q);
                a[2 * q] = aa.x; a[2 * q + 1] = aa.y;
            }
#pragma unroll
            for (int q = 0; q < 2; q++) {
                ulonglong2 bb = *(const ulonglong2*)((const unsigned long long*)
                                    (Bsf + k * 136 + tx * 8) + 2 * q);
                bq[2 * q] = bb.x; bq[2 * q + 1] = bb.y;
            }
#pragma unroll
            for (int i = 0; i < 8; i++)
#pragma unroll
                for (int j = 0; j < 4; j++)
                    ffma2(acc[i][j], a[i], bq[j]);
        }
        __syncthreads();
    }

    float* op = g_s1 + ((size_t)b * HID + h0 + ty * 8) * TT + t0 + tx * 8;
#pragma unroll
    for (int i = 0; i < 8; i++)
#pragma unroll
        for (int jj = 0; jj < 2; jj++) {
            ulonglong2 uv; uv.x = acc[i][2 * jj]; uv.y = acc[i][2 * jj + 1];
            *(ulonglong2*)(op + (size_t)i * TT + 4 * jj) = uv;
        }
}

// ---------------------------------------------------------------------------
// psp + spike for s1: thread per (b,h) row, sequential chain over t (bitwise
// same order), float4 reads, uint8 spike writes.
// ---------------------------------------------------------------------------
__global__ __launch_bounds__(128) void k_psp_s1() {
    int r = blockIdx.x * 128 + threadIdx.x;   // 0..16383
    const float4* pv = (const float4*)(g_s1 + (size_t)r * TT);
    uchar4* qv = (uchar4*)(g_s1u8 + (size_t)r * TT);
    float y = 0.0f;
#pragma unroll 8
    for (int t = 0; t < TT / 4; t++) {
        float4 v = pv[t];
        uchar4 s;
        y = fmaf(ALPHA_F, y, v.x); s.x = (y >= THETA_F) ? 1 : 0;
        y = fmaf(ALPHA_F, y, v.y); s.y = (y >= THETA_F) ? 1 : 0;
        y = fmaf(ALPHA_F, y, v.z); s.z = (y >= THETA_F) ? 1 : 0;
        y = fmaf(ALPHA_F, y, v.w); s.w = (y >= THETA_F) ? 1 : 0;
        qv[t] = s;
    }
}

// ---------------------------------------------------------------------------
// Branch1 layer2: a2[b,o,t] = sum_h W2[o,h] * s1u8[b,h,t]
// 32o(pad) x 64t tile, BK=32, 128 threads, 4x4 micro, FFMA2 packed.
// ---------------------------------------------------------------------------
__global__ __launch_bounds__(128) void k_gemm_b1l2(const float* __restrict__ W2) {
    __shared__ unsigned long long Wsd[32 * 36];  // dup pairs [k][o], stride 36 pairs
    __shared__ float Ssf[32 * 72];               // [k][t], stride 72 floats (36 pairs)

    const int b  = blockIdx.y;
    const int t0 = blockIdx.x * 64;
    const int tid = threadIdx.x;
    const int tx = tid & 15;   // t micro (4 t)
    const int ty = tid >> 4;   // o micro (4 o), ty 0..7
    const unsigned char* Sb = g_s1u8 + (size_t)b * HID * TT;

    unsigned long long acc[4][2];
#pragma unroll
    for (int i = 0; i < 4; i++) { acc[i][0] = 0ULL; acc[i][1] = 0ULL; }

    for (int k0 = 0; k0 < HID; k0 += 32) {
#pragma unroll
        for (int i = 0; i < 8; i++) {
            int idx = tid + 128 * i;       // 0..1023
            int o = idx >> 5, k = idx & 31;
            float v = (o < NOUT) ? W2[o * HID + k0 + k] : 0.0f;
            ((float2*)Wsd)[k * 36 + o] = make_float2(v, v);
        }
#pragma unroll
        for (int i = 0; i < 4; i++) {
            int idx = tid + 128 * i;       // 0..511
            int k = idx >> 4, tq = idx & 15;
            uchar4 u = *(const uchar4*)(Sb + (size_t)(k0 + k) * TT + t0 + tq * 4);
            *(float4*)&Ssf[k * 72 + tq * 4] =
                make_float4((float)u.x, (float)u.y, (float)u.z, (float)u.w);
        }
        __syncthreads();
#pragma unroll
        for (int k = 0; k < 32; k++) {
            unsigned long long a[4], bq[2];
            ulonglong2 aa = *(const ulonglong2*)(Wsd + k * 36 + ty * 4);
            a[0] = aa.x; a[1] = aa.y;
            ulonglong2 aa2 = *(const ulonglong2*)(Wsd + k * 36 + ty * 4 + 2);
            a[2] = aa2.x; a[3] = aa2.y;
            ulonglong2 bb = *(const ulonglong2*)((const unsigned long long*)
                                (Ssf + k * 72 + tx * 4));
            bq[0] = bb.x; bq[1] = bb.y;
#pragma unroll
            for (int i = 0; i < 4; i++) {
                ffma2(acc[i][0], a[i], bq[0]);
                ffma2(acc[i][1], a[i], bq[1]);
            }
        }
        __syncthreads();
    }

#pragma unroll
    for (int i = 0; i < 4; i++) {
        int o = ty * 4 + i;
        if (o < NOUT) {
            float* op = g_a2 + ((size_t)b * NOUT + o) * TT + t0 + tx * 4;
            *(unsigned long long*)(op)     = acc[i][0];
            *(unsigned long long*)(op + 2) = acc[i][1];
        }
    }
}

// ---------------------------------------------------------------------------
// Warp-per-row scan -> output. Lanes stage coalesced chunks + prefetch next;
// lane 0 runs the exact sequential fmaf chain from smem.
// ---------------------------------------------------------------------------
__device__ __forceinline__ void scan_rows(const float* __restrict__ in,
                                          float* __restrict__ out,
                                          int len, int out_off) {
    __shared__ float4 buf[8][32];
    const int w = threadIdx.x >> 5, lane = threadIdx.x & 31;
    const int row = blockIdx.x * 8 + w;          // grid sized to rows/8 exactly
    const float* ip = in + (size_t)row * len;
    float* op = out + (size_t)row * OUTT + out_off;
    const int nch = (len + 127) / 128;

    float y = 0.0f;
    int idx = lane * 4;
    float4 v = make_float4(0.f, 0.f, 0.f, 0.f);
    if (idx < len) v = *(const float4*)(ip + idx);

    for (int ch = 0; ch < nch; ch++) {
        buf[w][lane] = v;
        __syncwarp();
        int nidx = (ch + 1) * 128 + lane * 4;          // prefetch next chunk
        if (nidx < len) v = *(const float4*)(ip + nidx);
        if (lane == 0) {
            int n4 = (len - ch * 128) >> 2; if (n4 > 32) n4 = 32;
            for (int i = 0; i < n4; i++) {
                float4 u = buf[w][i]; float4 s;
                y = fmaf(ALPHA_F, y, u.x); s.x = (y >= THETA_F) ? 1.0f : 0.0f;
                y = fmaf(ALPHA_F, y, u.y); s.y = (y >= THETA_F) ? 1.0f : 0.0f;
                y = fmaf(ALPHA_F, y, u.z); s.z = (y >= THETA_F) ? 1.0f : 0.0f;
                y = fmaf(ALPHA_F, y, u.w); s.w = (y >= THETA_F) ? 1.0f : 0.0f;
                buf[w][i] = s;
            }
        }
        __syncwarp();
        int oi = ch * 128 + lane * 4;
        if (oi < len) *(float4*)(op + oi) = buf[w][lane];
        __syncwarp();
    }
}

__global__ __launch_bounds__(256) void k_scan_a2(float* __restrict__ out) {
    scan_rows(g_a2, out, TT, 0);
}
__global__ __launch_bounds__(256) void k_scan_l2(float* __restrict__ out) {
    scan_rows(g_l2, out, CIN, TT);
}

// ---------------------------------------------------------------------------
// Branch2 layer1: l1[b,c,h] = sum_t Wl1[h,t] * X[b,perm[c],t]
// 128h x 64c tile, BK=16, K=2048, 128 threads, 8x8 micro, FFMA2 packed.
// Epilogue stages through smem for coalesced [b][c][h] stores.
// ---------------------------------------------------------------------------
__global__ __launch_bounds__(128) void k_gemm_b2l1(const float* __restrict__ X,
                                                   const float* __restrict__ Wl1,
                                                   const int* __restrict__ perm) {
    __shared__ union {
        struct { unsigned long long Asd[16 * 132]; float Bsf[16 * 72]; } s;
        float Ct[64 * 129];
    } sm;
    __shared__ int prow[64];

    const int b  = blockIdx.z;
    const int h0 = blockIdx.y * 128;
    const int c0 = blockIdx.x * 64;
    const int tid = threadIdx.x;
    const int tx = tid & 7;    // c micro (8 c)
    const int ty = tid >> 3;   // h micro (8 h), 0..15
    const float* Xb = X + (size_t)b * CIN * TT;

    if (tid < 64) {
        int c = c0 + tid;
        prow[tid] = (c < CIN) ? perm[c] : 0;
    }
    __syncthreads();

    unsigned long long acc[8][4];
#pragma unroll
    for (int i = 0; i < 8; i++)
#pragma unroll
        for (int j = 0; j < 4; j++) acc[i][j] = 0ULL;

    for (int k0 = 0; k0 < TT; k0 += 16) {
        // A slab: Wl1[h0..+127][k0..+15] (K contiguous) -> dup pairs
#pragma unroll
        for (int i = 0; i < 4; i++) {
            int idx = tid + 128 * i;        // 0..511
            int h = idx >> 2, kq = idx & 3;
            float4 wv = *(const float4*)(Wl1 + (size_t)(h0 + h) * TT + k0 + kq * 4);
            ((float2*)sm.s.Asd)[(kq * 4 + 0) * 132 + h] = make_float2(wv.x, wv.x);
            ((float2*)sm.s.Asd)[(kq * 4 + 1) * 132 + h] = make_float2(wv.y, wv.y);
            ((float2*)sm.s.Asd)[(kq * 4 + 2) * 132 + h] = make_float2(wv.z, wv.z);
            ((float2*)sm.s.Asd)[(kq * 4 + 3) * 132 + h] = make_float2(wv.w, wv.w);
        }
        // B slab: X[perm[c]][k0..+15]
#pragma unroll
        for (int i = 0; i < 2; i++) {
            int idx = tid + 128 * i;        // 0..255
            int c = idx >> 2, kq = idx & 3;
            float4 v = make_float4(0.f, 0.f, 0.f, 0.f);
            if (c0 + c < CIN)
                v = *(const float4*)(Xb + (size_t)prow[c] * TT + k0 + kq * 4);
            sm.s.Bsf[(kq * 4 + 0) * 72 + c] = v.x;
            sm.s.Bsf[(kq * 4 + 1) * 72 + c] = v.y;
            sm.s.Bsf[(kq * 4 + 2) * 72 + c] = v.z;
            sm.s.Bsf[(kq * 4 + 3) * 72 + c] = v.w;
        }
        __syncthreads();
#pragma unroll
        for (int k = 0; k < 16; k++) {
            unsigned long long a[8], bq[4];
#pragma unroll
            for (int q = 0; q < 4; q++) {
                ulonglong2 aa = *(const ulonglong2*)(sm.s.Asd + k * 132 + ty * 8 + 2 * q);
                a[2 * q] = aa.x; a[2 * q + 1] = aa.y;
            }
#pragma unroll
            for (int q = 0; q < 2; q++) {
                ulonglong2 bb = *(const ulonglong2*)((const unsigned long long*)
                                    (sm.s.Bsf + k * 72 + tx * 8) + 2 * q);
                bq[2 * q] = bb.x; bq[2 * q + 1] = bb.y;
            }
#pragma unroll
            for (int i = 0; i < 8; i++)
#pragma unroll
                for (int j = 0; j < 4; j++)
                    ffma2(acc[i][j], a[i], bq[j]);
        }
        __syncthreads();
    }

    // stage transposed tile in smem, then coalesced store to [b][c][h]
#pragma unroll
    for (int i = 0; i < 8; i++)
#pragma unroll
        for (int j = 0; j < 4; j++) {
            float2 f = *(float2*)&acc[i][j];
            int cl = tx * 8 + 2 * j;
            sm.Ct[cl * 129 + ty * 8 + i]       = f.x;
            sm.Ct[(cl + 1) * 129 + ty * 8 + i] = f.y;
        }
    __syncthreads();
#pragma unroll 8
    for (int it = 0; it < 64; it++) {
        int idx = tid + 128 * it;             // 0..8191
        int cl = idx >> 7, hh = idx & 127;
        if (c0 + cl < CIN)
            g_l1[((size_t)b * CIN + c0 + cl) * HID + h0 + hh] = sm.Ct[cl * 129 + hh];
    }
}

// ---------------------------------------------------------------------------
// psp + spike for l1 (scan over c, layout [b][c][h] -> coalesced over h).
// ---------------------------------------------------------------------------
__global__ __launch_bounds__(128) void k_psp_l1() {
    int r = blockIdx.x * 128 + threadIdx.x;   // 0..16383, b = r>>9, h = r&511
    float* base = g_l1 + (size_t)(r >> 9) * CIN * HID + (r & (HID - 1));
    float y = 0.0f;
#pragma unroll 4
    for (int c = 0; c < CIN; c++) {
        y = fmaf(ALPHA_F, y, base[(size_t)c * HID]);
        base[(size_t)c * HID] = (y >= THETA_F) ? 1.0f : 0.0f;
    }
}

// ---------------------------------------------------------------------------
// Branch2 layer2: l2[b,o,c] = sum_h Wl2[o,h] * l1[b,c,h] (h contiguous now).
// ---------------------------------------------------------------------------
__global__ __launch_bounds__(160) void k_gemm_b2l2(const float* __restrict__ Wl2) {
    __shared__ float Ws[4 * HID];
    const int og = blockIdx.x;   // 0..4
    const int b  = blockIdx.y;
    const int tid = threadIdx.x;

    for (int idx = tid; idx < 4 * HID; idx += 160)
        Ws[idx] = Wl2[(og * 4 + (idx >> 9)) * HID + (idx & (HID - 1))];
    __syncthreads();

    const int c = tid;
    if (c >= CIN) return;
    const float* Lb = g_l1 + ((size_t)b * CIN + c) * HID;
    float acc[4] = {0.f, 0.f, 0.f, 0.f};

#pragma unroll 4
    for (int h = 0; h < HID; h += 4) {
        float4 xv = *(const float4*)(Lb + h);
#pragma unroll
        for (int o = 0; o < 4; o++) {
            const float4 w = *(const float4*)&Ws[o * HID + h];
            acc[o] = fmaf(w.x, xv.x, acc[o]);
            acc[o] = fmaf(w.y, xv.y, acc[o]);
            acc[o] = fmaf(w.z, xv.z, acc[o]);
            acc[o] = fmaf(w.w, xv.w, acc[o]);
        }
    }
#pragma unroll
    for (int o = 0; o < 4; o++)
        g_l2[((size_t)b * NOUT + og * 4 + o) * CIN + c] = acc[o];
}

// ---------------------------------------------------------------------------
// Launch
// ---------------------------------------------------------------------------
extern "C" void kernel_launch(void* const* d_in, const int* in_sizes, int n_in,
                              void* d_out, int out_size) {
    (void)in_sizes; (void)n_in; (void)out_size;
    const float* X    = (const float*)d_in[0];
    const float* W1   = (const float*)d_in[1];
    const float* W2   = (const float*)d_in[2];
    const float* Wl1  = (const float*)d_in[3];
    const float* Wl2  = (const float*)d_in[4];
    const int*   perm = (const int*)d_in[5];
    float* out = (float*)d_out;

    // Branch 1
    k_gemm_b1l1<<<dim3(TT / 128, HID / 128, BB), 256>>>(X, W1);
    k_psp_s1<<<BB * HID / 128, 128>>>();
    k_gemm_b1l2<<<dim3(TT / 64, BB), 128>>>(W2);
    k_scan_a2<<<BB * NOUT / 8, 256>>>(out);

    // Branch 2
    k_gemm_b2l1<<<dim3(3, HID / 128, BB), 128>>>(X, Wl1, perm);
    k_psp_l1<<<BB * HID / 128, 128>>>();
    k_gemm_b2l2<<<dim3(5, BB), 160>>>(Wl2);
    k_scan_l2<<<BB * NOUT / 8, 256>>>(out);
}